// round 14
// baseline (speedup 1.0000x reference)
#include <cuda_runtime.h>
#include <cuda_fp16.h>

#define C_CH    256
#define NBINS   49
#define SPOS    14
#define ROW_H2  132                      // half2 per staging row (128 + pad)
#define STAGE_H2 (NBINS * ROW_H2)        // 6468 half2 = 25872 B
#define TAB_ENT (NBINS * 16)             // per-level tap table: 784 entries
#define SMEM_DYN (STAGE_H2 * 4 + TAB_ENT * 8)   // 32144 B

#define L0_TILES  8192                   // 2048 pixel-tiles x 4 channel-tiles
#define L0_GRID   256                    // persistent transpose blocks

// NHWC fp16 scratch for all 4 pyramid levels: 256 ch * 87040 pixels = 44.5 MB
__device__ __half g_h[22282240];
__device__ int    g_l0_done;             // arrive counter (L0_GRID arrivals)

__constant__ int   c_W[4]     = {256, 128, 64, 32};
__constant__ float c_scale[4] = {0.25f, 0.125f, 0.0625f, 0.03125f};
__constant__ int   c_base[4]  = {0, 65536, 81920, 86016};  // pixel offsets

__global__ void reset_flag() { g_l0_done = 0; }

// ---------------------------------------------------------------------------
// Levels 1..3 transpose (35 MB): NCHW fp32 -> NHWC fp16, 64-ch tiles.
// ---------------------------------------------------------------------------
__global__ void transpose_rest(const float* __restrict__ f1,
                               const float* __restrict__ f2,
                               const float* __restrict__ f3) {
    __shared__ float tile[32][65];       // [pixel][channel]
    int bx = blockIdx.x + 2048;
    const float* in; int HW, pix_base, hw0;
    if (bx < 2560)      { in = f1; HW = 16384; pix_base = 65536; hw0 = (bx - 2048) * 32; }
    else if (bx < 2688) { in = f2; HW = 4096;  pix_base = 81920; hw0 = (bx - 2560) * 32; }
    else                { in = f3; HW = 1024;  pix_base = 86016; hw0 = (bx - 2688) * 32; }
    int c0 = blockIdx.y * 64;
    int tx = threadIdx.x, ty = threadIdx.y;
#pragma unroll
    for (int k = 0; k < 8; ++k) {
        int ch = ty + k * 8;
        tile[tx][ch] = in[(size_t)(c0 + ch) * HW + hw0 + tx];
    }
    __syncthreads();
    __half2* g2 = (__half2*)g_h;
#pragma unroll
    for (int k = 0; k < 4; ++k) {
        int px = ty + k * 8;
        __half2 v = __floats2half2_rn(tile[px][2 * tx], tile[px][2 * tx + 1]);
        g2[((size_t)(pix_base + hw0 + px) * C_CH + c0) / 2 + tx] = v;
    }
}

// ---------------------------------------------------------------------------
// Persistent level-0 transpose (96 MB): 256 blocks grid-stride over 8192
// tiles. Small grid -> occupies only 256 SM slots, runs CONCURRENTLY with
// the roi kernel. Arrives on g_l0_done when done + globally visible.
// ---------------------------------------------------------------------------
__global__ void transpose_l0(const float* __restrict__ f0) {
    __shared__ float tile[32][65];
    int tx = threadIdx.x, ty = threadIdx.y;
    __half2* g2 = (__half2*)g_h;
    for (int task = blockIdx.x; task < L0_TILES; task += gridDim.x) {
        int hw0 = (task & 2047) * 32;
        int c0  = (task >> 11) * 64;
        __syncthreads();                 // protect tile reuse across iterations
#pragma unroll
        for (int k = 0; k < 8; ++k) {
            int ch = ty + k * 8;
            tile[tx][ch] = f0[(size_t)(c0 + ch) * 65536 + hw0 + tx];
        }
        __syncthreads();
#pragma unroll
        for (int k = 0; k < 4; ++k) {
            int px = ty + k * 8;
            __half2 v = __floats2half2_rn(tile[px][2 * tx], tile[px][2 * tx + 1]);
            g2[((size_t)(hw0 + px) * C_CH + c0) / 2 + tx] = v;
        }
    }
    __threadfence();
    __syncthreads();
    if (tx == 0 && ty == 0) atomicAdd(&g_l0_done, 1);
}

// process 4 taps (distinct registers per expansion site) — R9 hot loop
#define TAP_GROUP(S)                                                          \
    {                                                                         \
        int2 e0 = tp[(S) + 0], e1 = tp[(S) + 1];                              \
        int2 e2 = tp[(S) + 2], e3 = tp[(S) + 3];                              \
        uint4 v0 = FL[e0.x], v1 = FL[e1.x], v2 = FL[e2.x], v3 = FL[e3.x];     \
        __half2 w0 = *(__half2*)&e0.y, w1 = *(__half2*)&e1.y;                 \
        __half2 w2 = *(__half2*)&e2.y, w3 = *(__half2*)&e3.y;                 \
        const __half2* q0 = (const __half2*)&v0;                              \
        const __half2* q1 = (const __half2*)&v1;                              \
        const __half2* q2 = (const __half2*)&v2;                              \
        const __half2* q3 = (const __half2*)&v3;                              \
        __half2 c0h = __hmul2(w0, q0[0]), c1h = __hmul2(w0, q0[1]);           \
        __half2 c2h = __hmul2(w0, q0[2]), c3h = __hmul2(w0, q0[3]);           \
        c0h = __hfma2(w1, q1[0], c0h); c1h = __hfma2(w1, q1[1], c1h);         \
        c2h = __hfma2(w1, q1[2], c2h); c3h = __hfma2(w1, q1[3], c3h);         \
        c0h = __hfma2(w2, q2[0], c0h); c1h = __hfma2(w2, q2[1], c1h);         \
        c2h = __hfma2(w2, q2[2], c2h); c3h = __hfma2(w2, q2[3], c3h);         \
        c0h = __hfma2(w3, q3[0], c0h); c1h = __hfma2(w3, q3[1], c1h);         \
        c2h = __hfma2(w3, q3[2], c2h); c3h = __hfma2(w3, q3[3], c3h);         \
        float2 f0 = __half22float2(c0h), f1 = __half22float2(c1h);            \
        float2 f2 = __half22float2(c2h), f3 = __half22float2(c3h);            \
        a0 += f0.x; a1 += f0.y; a2 += f1.x; a3 += f1.y;                       \
        a4 += f2.x; a5 += f2.y; a6 += f3.x; a7 += f3.y;                       \
    }

// ---------------------------------------------------------------------------
// Main kernel: one block per roi; R9 guarded-group hot loop. Levels 3->0 so
// the concurrently-transposed level 0 is needed last; gate before level 0.
// ---------------------------------------------------------------------------
__global__ __launch_bounds__(256, 5)
void roi_max_kernel(const float* __restrict__ rois, float* __restrict__ out) {
    extern __shared__ __align__(16) char dyn[];
    __half2* sh2 = (__half2*)dyn;                       // staging [49][132]
    int2*    tab = (int2*)(dyn + STAGE_H2 * 4);         // [49][16] current level

    __shared__ int   s_lo[2][4][SPOS];
    __shared__ int   s_hi[2][4][SPOS];
    __shared__ float s_wl[2][4][SPOS];   // pre-scaled by 0.5 (bin-average fold)
    __shared__ float s_wh[2][4][SPOS];
    __shared__ int   s_cnt[NBINS];       // padded tap count per bin (this level)

    const int n = blockIdx.x;
    const int t = threadIdx.x;

    // --- phase 1: 1D bilinear taps for ALL levels (tiny)
    if (t < 112) {
        int lvl = t / 28;
        int rem = t % 28;
        int dim = rem / 14;
        int s   = rem % 14;
        float scale = c_scale[lvl];
        float size  = (float)c_W[lvl];
        float start = rois[n * 5 + 1 + dim] * scale;
        float end   = rois[n * 5 + 3 + dim] * scale;
        float len   = fmaxf(end - start, 1.0f);
        float gpos  = (float)(s >> 1) + ((s & 1) ? 0.75f : 0.25f);
        float coord = start + gpos * (len * (1.0f / 7.0f));
        bool valid  = (coord > -1.0f) && (coord < size);
        float cc = fminf(fmaxf(coord, 0.0f), size - 1.0f);
        int lo = (int)cc;
        int hi = min(lo + 1, c_W[lvl] - 1);
        float wh = cc - (float)lo;
        float wl = 1.0f - wh;
        if (!valid) { wl = 0.0f; wh = 0.0f; }
        s_lo[dim][lvl][s] = lo;
        s_hi[dim][lvl][s] = hi;
        s_wl[dim][lvl][s] = wl * 0.5f;
        s_wh[dim][lvl][s] = wh * 0.5f;
    }
    __syncthreads();

    const int g  = t >> 5;                 // warp id 0..7
    const int o  = t & 31;                 // channel octet
    const int p0 = (NBINS * g) >> 3;
    const int p1 = (NBINS * (g + 1)) >> 3;

    const uint4* __restrict__ F = (const uint4*)g_h;

#pragma unroll
    for (int li = 0; li < 4; ++li) {
        const int l = 3 - li;              // 3,2,1,0: level 0 last

        // gate: concurrently-running L0 transpose must be complete
        if (l == 0) {
            if (t == 0) {
                while (*(volatile int*)&g_l0_done < L0_GRID) __nanosleep(256);
            }
            __syncthreads();
            __threadfence_block();
        }

        // --- per-level table build: 49 threads, registers only, then smem
        if (t < NBINS) {
            int by = t / 7, bx = t - (t / 7) * 7;
            int   px[16];
            float w[16];
#pragma unroll
            for (int e = 0; e < 16; ++e) {
                int sy = e >> 3, sx = (e >> 2) & 1, ty = (e >> 1) & 1, tx = e & 1;
                int iy = 2 * by + sy, ix = 2 * bx + sx;
                int   yi = ty ? s_hi[1][l][iy] : s_lo[1][l][iy];
                float wy = ty ? s_wh[1][l][iy] : s_wl[1][l][iy];
                int   xi = tx ? s_hi[0][l][ix] : s_lo[0][l][ix];
                float wx = tx ? s_wh[0][l][ix] : s_wl[0][l][ix];
                px[e] = (yi * c_W[l] + xi) * 32;
                w[e]  = wy * wx;
            }
            // triangular merge: later dup folds into earliest copy
#pragma unroll
            for (int i = 1; i < 16; ++i) {
#pragma unroll
                for (int j = 0; j < 16; ++j) {
                    if (j < i) {
                        bool hit = (px[i] >= 0) && (px[j] == px[i]);
                        if (hit) { w[j] += w[i]; px[i] = -1; }
                    }
                }
            }
            int m = 0;
            int base = t * 16;
#pragma unroll
            for (int i = 0; i < 16; ++i) {
                if (px[i] >= 0) {
                    __half2 w2 = __float2half2_rn(w[i]);
                    int2 e; e.x = px[i]; e.y = *(int*)&w2;
                    tab[base + m] = e; ++m;
                }
            }
            int m4 = (m + 3) & ~3;
            for (int j = m; j < m4; ++j) { int2 z; z.x = 0; z.y = 0; tab[base + j] = z; }
            s_cnt[t] = m4;
        }
        __syncthreads();

        // --- hot loop for this level (R9 guarded groups)
        const uint4* __restrict__ FL = F + (size_t)c_base[l] * 32 + o;
        for (int p = p0; p < p1; ++p) {
            const int2* tp = tab + p * 16;
            const int m4 = s_cnt[p];
            float a0 = 0.f, a1 = 0.f, a2 = 0.f, a3 = 0.f;
            float a4 = 0.f, a5 = 0.f, a6 = 0.f, a7 = 0.f;
            TAP_GROUP(0)
            if (m4 > 4)  TAP_GROUP(4)
            if (m4 > 8)  TAP_GROUP(8)
            if (m4 > 12) TAP_GROUP(12)
            __half2 r0 = __floats2half2_rn(a0, a1);
            __half2 r1 = __floats2half2_rn(a2, a3);
            __half2 r2 = __floats2half2_rn(a4, a5);
            __half2 r3 = __floats2half2_rn(a6, a7);
            uint4* dst = (uint4*)(sh2 + p * ROW_H2 + o * 4);
            if (l == 3) {                          // first processed level
                uint4 nw;
                ((__half2*)&nw)[0] = r0; ((__half2*)&nw)[1] = r1;
                ((__half2*)&nw)[2] = r2; ((__half2*)&nw)[3] = r3;
                *dst = nw;
            } else {
                uint4 old = *dst;
                __half2* oh = (__half2*)&old;
                oh[0] = __hmax2(oh[0], r0); oh[1] = __hmax2(oh[1], r1);
                oh[2] = __hmax2(oh[2], r2); oh[3] = __hmax2(oh[3], r3);
                *dst = old;
            }
        }
        __syncthreads();   // table rebuilt next level; staging RMW complete
    }

    // coalesced drain: out[n][c][p]
    const __half* shh = (const __half*)sh2;
    float* __restrict__ O = out + (size_t)n * (C_CH * NBINS);
    for (int idx = t; idx < C_CH * NBINS; idx += 256) {
        int c = idx / 49;
        int p = idx - c * 49;
        O[idx] = __half2float(shh[p * (ROW_H2 * 2) + c]);
    }
}

// ---------------------------------------------------------------------------
extern "C" void kernel_launch(void* const* d_in, const int* in_sizes, int n_in,
                              void* d_out, int out_size) {
    const float* f0   = (const float*)d_in[0];
    const float* f1   = (const float*)d_in[1];
    const float* f2   = (const float*)d_in[2];
    const float* f3   = (const float*)d_in[3];
    const float* rois = (const float*)d_in[4];
    int nrois = in_sizes[4] / 5;

    // lazy one-time stream/event creation (first call is the uncaptured
    // correctness run, so these exist before graph capture begins)
    static cudaStream_t s2 = nullptr;
    static cudaEvent_t  e1 = nullptr, e2 = nullptr;
    if (!s2) {
        cudaStreamCreateWithFlags(&s2, cudaStreamNonBlocking);
        cudaEventCreateWithFlags(&e1, cudaEventDisableTiming);
        cudaEventCreateWithFlags(&e2, cudaEventDisableTiming);
    }

    // reset arrive counter FIRST (so ncu kernel-replay of roi sees flag set)
    reset_flag<<<1, 1>>>();

    // fork: persistent small-grid L0 transpose — enqueued BEFORE the big
    // grids, so its 256 blocks get SM slots first (FIFO dispatch), then run
    // concurrently with transpose_rest and the roi kernel.
    cudaEventRecord(e1, 0);
    cudaStreamWaitEvent(s2, e1, 0);
    transpose_l0<<<L0_GRID, dim3(32, 8), 0, s2>>>(f0);

    // levels 1-3 transpose (serial head, ~7us) then the roi kernel
    transpose_rest<<<dim3(672, 4), dim3(32, 8)>>>(f1, f2, f3);

    cudaFuncSetAttribute(roi_max_kernel,
                         cudaFuncAttributeMaxDynamicSharedMemorySize, SMEM_DYN);
    roi_max_kernel<<<nrois, 256, SMEM_DYN>>>(rois, (float*)d_out);

    // join fork for valid graph capture (no serial cost: l0 ends early)
    cudaEventRecord(e2, s2);
    cudaStreamWaitEvent(0, e2, 0);
}

// round 15
// speedup vs baseline: 1.1503x; 1.1503x over previous
#include <cuda_runtime.h>
#include <cuda_fp16.h>

#define C_CH    256
#define NBINS   49
#define SPOS    14
#define ROW_H2  132                      // half2 per staging row (128 + pad)
#define STAGE_H2 (NBINS * ROW_H2)        // 6468 half2 = 25872 B
#define TAB_ENT (NBINS * 16)             // per-level tap table: 784 entries
#define SMEM_DYN (STAGE_H2 * 4 + TAB_ENT * 8)   // 32144 B

// NHWC fp16 scratch for all 4 pyramid levels: 256 ch * 87040 pixels = 44.5 MB
__device__ __half g_h[22282240];

__constant__ int   c_W[4]     = {256, 128, 64, 32};
__constant__ float c_scale[4] = {0.25f, 0.125f, 0.0625f, 0.03125f};
__constant__ int   c_base[4]  = {0, 65536, 81920, 86016};  // pixel offsets

// ---------------------------------------------------------------------------
// Fused NCHW fp32 -> NHWC fp16 transpose, 64-ch tiles, 128B warp stores.
// ---------------------------------------------------------------------------
__global__ void transpose_all(const float* __restrict__ f0,
                              const float* __restrict__ f1,
                              const float* __restrict__ f2,
                              const float* __restrict__ f3) {
    __shared__ float tile[32][65];       // [pixel][channel]
    int bx = blockIdx.x;
    const float* in; int HW, pix_base, hw0;
    if (bx < 2048)      { in = f0; HW = 65536; pix_base = 0;     hw0 = bx * 32; }
    else if (bx < 2560) { in = f1; HW = 16384; pix_base = 65536; hw0 = (bx - 2048) * 32; }
    else if (bx < 2688) { in = f2; HW = 4096;  pix_base = 81920; hw0 = (bx - 2560) * 32; }
    else                { in = f3; HW = 1024;  pix_base = 86016; hw0 = (bx - 2688) * 32; }
    int c0 = blockIdx.y * 64;
    int tx = threadIdx.x, ty = threadIdx.y;
#pragma unroll
    for (int k = 0; k < 8; ++k) {
        int ch = ty + k * 8;
        tile[tx][ch] = in[(size_t)(c0 + ch) * HW + hw0 + tx];
    }
    __syncthreads();
    __half2* g2 = (__half2*)g_h;
#pragma unroll
    for (int k = 0; k < 4; ++k) {
        int px = ty + k * 8;
        __half2 v = __floats2half2_rn(tile[px][2 * tx], tile[px][2 * tx + 1]);
        g2[((size_t)(pix_base + hw0 + px) * C_CH + c0) / 2 + tx] = v;
    }
}

// process 4 taps, NO guards: dead taps have pix=0 (always-L1-hit line) and
// w=0 (exact zero contribution). Straight-line -> ptxas batches loads freely.
#define TAP_GROUP(S)                                                          \
    {                                                                         \
        int2 e0 = tp[(S) + 0], e1 = tp[(S) + 1];                              \
        int2 e2 = tp[(S) + 2], e3 = tp[(S) + 3];                              \
        uint4 v0 = FL[e0.x], v1 = FL[e1.x], v2 = FL[e2.x], v3 = FL[e3.x];     \
        __half2 w0 = *(__half2*)&e0.y, w1 = *(__half2*)&e1.y;                 \
        __half2 w2 = *(__half2*)&e2.y, w3 = *(__half2*)&e3.y;                 \
        const __half2* q0 = (const __half2*)&v0;                              \
        const __half2* q1 = (const __half2*)&v1;                              \
        const __half2* q2 = (const __half2*)&v2;                              \
        const __half2* q3 = (const __half2*)&v3;                              \
        __half2 c0h = __hmul2(w0, q0[0]), c1h = __hmul2(w0, q0[1]);           \
        __half2 c2h = __hmul2(w0, q0[2]), c3h = __hmul2(w0, q0[3]);           \
        c0h = __hfma2(w1, q1[0], c0h); c1h = __hfma2(w1, q1[1], c1h);         \
        c2h = __hfma2(w1, q1[2], c2h); c3h = __hfma2(w1, q1[3], c3h);         \
        c0h = __hfma2(w2, q2[0], c0h); c1h = __hfma2(w2, q2[1], c1h);         \
        c2h = __hfma2(w2, q2[2], c2h); c3h = __hfma2(w2, q2[3], c3h);         \
        c0h = __hfma2(w3, q3[0], c0h); c1h = __hfma2(w3, q3[1], c1h);         \
        c2h = __hfma2(w3, q3[2], c2h); c3h = __hfma2(w3, q3[3], c3h);         \
        float2 f0 = __half22float2(c0h), f1 = __half22float2(c1h);            \
        float2 f2 = __half22float2(c2h), f3 = __half22float2(c3h);            \
        a0 += f0.x; a1 += f0.y; a2 += f1.x; a3 += f1.y;                       \
        a4 += f2.x; a5 += f2.y; a6 += f3.x; a7 += f3.y;                       \
    }

// ---------------------------------------------------------------------------
// Main kernel: one block per roi. Per-level register-built dedup'd tap table,
// fully zero-padded to 16; branch-free hot loop at 64-reg budget for MLP.
// ---------------------------------------------------------------------------
__global__ __launch_bounds__(256, 4)
void roi_max_kernel(const float* __restrict__ rois, float* __restrict__ out) {
    extern __shared__ __align__(16) char dyn[];
    __half2* sh2 = (__half2*)dyn;                       // staging [49][132]
    int2*    tab = (int2*)(dyn + STAGE_H2 * 4);         // [49][16] current level

    __shared__ int   s_lo[2][4][SPOS];
    __shared__ int   s_hi[2][4][SPOS];
    __shared__ float s_wl[2][4][SPOS];   // pre-scaled by 0.5 (bin-average fold)
    __shared__ float s_wh[2][4][SPOS];

    const int n = blockIdx.x;
    const int t = threadIdx.x;

    // --- phase 1: 1D bilinear taps for ALL levels (tiny)
    if (t < 112) {
        int lvl = t / 28;
        int rem = t % 28;
        int dim = rem / 14;
        int s   = rem % 14;
        float scale = c_scale[lvl];
        float size  = (float)c_W[lvl];
        float start = rois[n * 5 + 1 + dim] * scale;
        float end   = rois[n * 5 + 3 + dim] * scale;
        float len   = fmaxf(end - start, 1.0f);
        float gpos  = (float)(s >> 1) + ((s & 1) ? 0.75f : 0.25f);
        float coord = start + gpos * (len * (1.0f / 7.0f));
        bool valid  = (coord > -1.0f) && (coord < size);
        float cc = fminf(fmaxf(coord, 0.0f), size - 1.0f);
        int lo = (int)cc;
        int hi = min(lo + 1, c_W[lvl] - 1);
        float wh = cc - (float)lo;
        float wl = 1.0f - wh;
        if (!valid) { wl = 0.0f; wh = 0.0f; }
        s_lo[dim][lvl][s] = lo;
        s_hi[dim][lvl][s] = hi;
        s_wl[dim][lvl][s] = wl * 0.5f;
        s_wh[dim][lvl][s] = wh * 0.5f;
    }
    __syncthreads();

    const int g  = t >> 5;                 // warp id 0..7
    const int o  = t & 31;                 // channel octet
    const int p0 = (NBINS * g) >> 3;
    const int p1 = (NBINS * (g + 1)) >> 3;

    const uint4* __restrict__ F = (const uint4*)g_h;

#pragma unroll
    for (int l = 0; l < 4; ++l) {
        // --- per-level table build: 49 threads, registers only, then smem
        if (t < NBINS) {
            int by = t / 7, bx = t - (t / 7) * 7;
            int   px[16];
            float w[16];
#pragma unroll
            for (int e = 0; e < 16; ++e) {
                int sy = e >> 3, sx = (e >> 2) & 1, ty = (e >> 1) & 1, tx = e & 1;
                int iy = 2 * by + sy, ix = 2 * bx + sx;
                int   yi = ty ? s_hi[1][l][iy] : s_lo[1][l][iy];
                float wy = ty ? s_wh[1][l][iy] : s_wl[1][l][iy];
                int   xi = tx ? s_hi[0][l][ix] : s_lo[0][l][ix];
                float wx = tx ? s_wh[0][l][ix] : s_wl[0][l][ix];
                px[e] = (yi * c_W[l] + xi) * 32;
                w[e]  = wy * wx;
            }
            // triangular merge: later dup folds into earliest copy
#pragma unroll
            for (int i = 1; i < 16; ++i) {
#pragma unroll
                for (int j = 0; j < 16; ++j) {
                    if (j < i) {
                        bool hit = (px[i] >= 0) && (px[j] == px[i]);
                        if (hit) { w[j] += w[i]; px[i] = -1; }
                    }
                }
            }
            int m = 0;
            int base = t * 16;
#pragma unroll
            for (int i = 0; i < 16; ++i) {
                if (px[i] >= 0) {
                    __half2 w2 = __float2half2_rn(w[i]);
                    int2 e; e.x = px[i]; e.y = *(int*)&w2;
                    tab[base + m] = e; ++m;
                }
            }
            for (int j = m; j < 16; ++j) {   // full zero-pad: pix 0, w 0
                int2 z; z.x = 0; z.y = 0; tab[base + j] = z;
            }
        }
        __syncthreads();

        // --- hot loop for this level: branch-free, 16 unconditional taps
        const uint4* __restrict__ FL = F + (size_t)c_base[l] * 32 + o;
        for (int p = p0; p < p1; ++p) {
            const int2* tp = tab + p * 16;
            float a0 = 0.f, a1 = 0.f, a2 = 0.f, a3 = 0.f;
            float a4 = 0.f, a5 = 0.f, a6 = 0.f, a7 = 0.f;
            TAP_GROUP(0)
            TAP_GROUP(4)
            TAP_GROUP(8)
            TAP_GROUP(12)
            __half2 r0 = __floats2half2_rn(a0, a1);
            __half2 r1 = __floats2half2_rn(a2, a3);
            __half2 r2 = __floats2half2_rn(a4, a5);
            __half2 r3 = __floats2half2_rn(a6, a7);
            uint4* dst = (uint4*)(sh2 + p * ROW_H2 + o * 4);
            if (l == 0) {
                uint4 nw;
                ((__half2*)&nw)[0] = r0; ((__half2*)&nw)[1] = r1;
                ((__half2*)&nw)[2] = r2; ((__half2*)&nw)[3] = r3;
                *dst = nw;
            } else {
                uint4 old = *dst;
                __half2* oh = (__half2*)&old;
                oh[0] = __hmax2(oh[0], r0); oh[1] = __hmax2(oh[1], r1);
                oh[2] = __hmax2(oh[2], r2); oh[3] = __hmax2(oh[3], r3);
                *dst = old;
            }
        }
        __syncthreads();   // table rebuilt next level; staging RMW complete
    }

    // coalesced drain: out[n][c][p]
    const __half* shh = (const __half*)sh2;
    float* __restrict__ O = out + (size_t)n * (C_CH * NBINS);
    for (int idx = t; idx < C_CH * NBINS; idx += 256) {
        int c = idx / 49;
        int p = idx - c * 49;
        O[idx] = __half2float(shh[p * (ROW_H2 * 2) + c]);
    }
}

// ---------------------------------------------------------------------------
extern "C" void kernel_launch(void* const* d_in, const int* in_sizes, int n_in,
                              void* d_out, int out_size) {
    const float* f0   = (const float*)d_in[0];
    const float* f1   = (const float*)d_in[1];
    const float* f2   = (const float*)d_in[2];
    const float* f3   = (const float*)d_in[3];
    const float* rois = (const float*)d_in[4];
    int nrois = in_sizes[4] / 5;

    transpose_all<<<dim3(2720, 4), dim3(32, 8)>>>(f0, f1, f2, f3);

    cudaFuncSetAttribute(roi_max_kernel,
                         cudaFuncAttributeMaxDynamicSharedMemorySize, SMEM_DYN);
    roi_max_kernel<<<nrois, 256, SMEM_DYN>>>(rois, (float*)d_out);
}